// round 1
// baseline (speedup 1.0000x reference)
#include <cuda_runtime.h>

#define B_   8
#define N_   1024
#define H_   12
#define D_   64
#define DIM_ 768
#define BH_  (B_*H_)

// Scratch (device globals: no allocation allowed in kernel_launch)
__device__ float g_q[(size_t)BH_ * N_ * D_];   // [b*H+h][n][d], pre-scaled by D^-0.5
__device__ float g_k[(size_t)BH_ * N_ * D_];   // [b*H+h][n][d]
__device__ float g_x[(size_t)B_ * N_ * DIM_];  // attention output, (b,n, h*64+d)

// ---------------------------------------------------------------------------
// LayerNorm on q and k heads. One warp per (b,h,n): 64 elems -> 2 per lane.
// ---------------------------------------------------------------------------
__global__ __launch_bounds__(256) void ln_kernel(
    const float* __restrict__ QKV,
    const float* __restrict__ qw, const float* __restrict__ qb,
    const float* __restrict__ kw, const float* __restrict__ kb)
{
    int gw   = (blockIdx.x * blockDim.x + threadIdx.x) >> 5;
    int lane = threadIdx.x & 31;
    int n  = gw & (N_ - 1);
    int bh = gw >> 10;           // b*H + h
    int h  = bh % H_;
    int b  = bh / H_;

    const float* base = QKV + ((size_t)(b * N_ + n)) * (3 * DIM_) + h * D_;
    float q0 = base[lane],        q1 = base[lane + 32];
    float k0 = base[DIM_ + lane], k1 = base[DIM_ + lane + 32];

    float sq = q0 + q1, sk = k0 + k1;
    #pragma unroll
    for (int o = 16; o; o >>= 1) {
        sq += __shfl_xor_sync(0xffffffffu, sq, o);
        sk += __shfl_xor_sync(0xffffffffu, sk, o);
    }
    float muq = sq * (1.f / 64.f), muk = sk * (1.f / 64.f);
    float dq0 = q0 - muq, dq1 = q1 - muq;
    float dk0 = k0 - muk, dk1 = k1 - muk;
    float vq = dq0 * dq0 + dq1 * dq1;
    float vk = dk0 * dk0 + dk1 * dk1;
    #pragma unroll
    for (int o = 16; o; o >>= 1) {
        vq += __shfl_xor_sync(0xffffffffu, vq, o);
        vk += __shfl_xor_sync(0xffffffffu, vk, o);
    }
    float rq = rsqrtf(vq * (1.f / 64.f) + 1e-5f);
    float rk = rsqrtf(vk * (1.f / 64.f) + 1e-5f);
    const float scale = 0.125f;  // 64^-0.5 folded into q

    size_t ro = ((size_t)bh * N_ + n) * D_;
    g_q[ro + lane]      = (dq0 * rq * qw[lane]      + qb[lane])      * scale;
    g_q[ro + lane + 32] = (dq1 * rq * qw[lane + 32] + qb[lane + 32]) * scale;
    g_k[ro + lane]      =  dk0 * rk * kw[lane]      + kb[lane];
    g_k[ro + lane + 32] =  dk1 * rk * kw[lane + 32] + kb[lane + 32];
}

// ---------------------------------------------------------------------------
// Flash attention, BM=BN=64, 256 threads, 4x4 register fragments.
// Smem operands stored transposed [d][row] with XOR swizzle (d&12)<<1 so both
// the fills and the inner-loop LDS.128 are bank-conflict-free.
// Kt and Pt share one 16KB buffer (Kt dead after S-GEMM).
// ---------------------------------------------------------------------------
__global__ __launch_bounds__(256) void attn_kernel(const float* __restrict__ QKV)
{
    __shared__ float Qt [64][64];  // [d][qrow], swizzled
    __shared__ float KPt[64][64];  // phase 1: Kt [d][krow] swizzled; phase 2: Pt [j][i] swizzled
    __shared__ float Vs [64][64];  // [krow][d], natural

    int qt = blockIdx.x;           // 0..15 query tile
    int bh = blockIdx.y;           // 0..95
    int b = bh / H_, h = bh % H_;
    int tid = threadIdx.x;
    int tx = tid & 15, ty = tid >> 4;

    // ---- load Q tile (transposed + swizzled) ----
    {
        int r  = tid >> 2;             // tile row 0..63
        int c0 = (tid & 3) * 4;        // head-dim base
        const float* src = g_q + ((size_t)bh * N_ + qt * 64 + r) * D_;
        #pragma unroll
        for (int it = 0; it < 4; it++) {
            int d0 = c0 + it * 16;
            float4 v = *(const float4*)(src + d0);
            float* dst = &Qt[d0][r ^ ((d0 & 12) << 1)];
            dst[0] = v.x; dst[64] = v.y; dst[128] = v.z; dst[192] = v.w;
        }
    }

    float m[4], l[4], o[4][4];
    #pragma unroll
    for (int r = 0; r < 4; r++) {
        m[r] = -1e30f; l[r] = 0.f;
        #pragma unroll
        for (int c = 0; c < 4; c++) o[r][c] = 0.f;
    }

    const float* vbase = QKV + (size_t)b * N_ * (3 * DIM_) + 2 * DIM_ + h * D_;

    for (int kt = 0; kt < N_ / 64; kt++) {
        __syncthreads();  // prior iteration fully consumed KPt/Vs
        // ---- fill K tile (transposed+swizzled) and V tile (natural) ----
        {
            int r  = tid >> 2;
            int c0 = (tid & 3) * 4;
            const float* ksrc = g_k + ((size_t)bh * N_ + kt * 64 + r) * D_;
            const float* vsrc = vbase + (size_t)(kt * 64 + r) * (3 * DIM_);
            #pragma unroll
            for (int it = 0; it < 4; it++) {
                int d0 = c0 + it * 16;
                float4 kv = *(const float4*)(ksrc + d0);
                float* dst = &KPt[d0][r ^ ((d0 & 12) << 1)];
                dst[0] = kv.x; dst[64] = kv.y; dst[128] = kv.z; dst[192] = kv.w;
                *(float4*)&Vs[r][d0] = *(const float4*)(vsrc + d0);
            }
        }
        __syncthreads();

        // ---- S = Q * K^T (scale already folded into Q) ----
        float sf[4][4];
        #pragma unroll
        for (int r = 0; r < 4; r++)
            #pragma unroll
            for (int c = 0; c < 4; c++) sf[r][c] = 0.f;

        #pragma unroll 16
        for (int d = 0; d < 64; d++) {
            int s = (d & 12) << 1;
            float4 q4 = *(const float4*)&Qt [d][(ty * 4) ^ s];
            float4 k4 = *(const float4*)&KPt[d][(tx * 4) ^ s];
            float qa[4] = {q4.x, q4.y, q4.z, q4.w};
            float ka[4] = {k4.x, k4.y, k4.z, k4.w};
            #pragma unroll
            for (int r = 0; r < 4; r++)
                #pragma unroll
                for (int c = 0; c < 4; c++) sf[r][c] += qa[r] * ka[c];
        }

        // ---- online softmax update ----
        float mt[4], al[4], rs[4];
        #pragma unroll
        for (int r = 0; r < 4; r++) {
            mt[r] = fmaxf(fmaxf(sf[r][0], sf[r][1]), fmaxf(sf[r][2], sf[r][3]));
            #pragma unroll
            for (int off = 8; off; off >>= 1)
                mt[r] = fmaxf(mt[r], __shfl_xor_sync(0xffffffffu, mt[r], off));
            float mn = fmaxf(m[r], mt[r]);
            al[r] = __expf(m[r] - mn);
            m[r]  = mn;
        }
        #pragma unroll
        for (int r = 0; r < 4; r++) {
            rs[r] = 0.f;
            #pragma unroll
            for (int c = 0; c < 4; c++) {
                sf[r][c] = __expf(sf[r][c] - m[r]);
                rs[r] += sf[r][c];
            }
            #pragma unroll
            for (int off = 8; off; off >>= 1)
                rs[r] += __shfl_xor_sync(0xffffffffu, rs[r], off);
            l[r] = l[r] * al[r] + rs[r];
            #pragma unroll
            for (int c = 0; c < 4; c++) o[r][c] *= al[r];
        }

        __syncthreads();  // everyone done reading Kt before Pt overwrites it
        // ---- store P transposed [j][i], swizzled by j ----
        #pragma unroll
        for (int c = 0; c < 4; c++) {
            int j = tx * 4 + c;
            int s = (j & 12) << 1;
            *(float4*)&KPt[j][(ty * 4) ^ s] =
                make_float4(sf[0][c], sf[1][c], sf[2][c], sf[3][c]);
        }
        __syncthreads();

        // ---- O += P * V ----
        #pragma unroll 16
        for (int j = 0; j < 64; j++) {
            int s = (j & 12) << 1;
            float4 p4 = *(const float4*)&KPt[j][(ty * 4) ^ s];
            float4 v4 = *(const float4*)&Vs[j][tx * 4];
            float pa[4] = {p4.x, p4.y, p4.z, p4.w};
            float va[4] = {v4.x, v4.y, v4.z, v4.w};
            #pragma unroll
            for (int r = 0; r < 4; r++)
                #pragma unroll
                for (int c = 0; c < 4; c++) o[r][c] += pa[r] * va[c];
        }
    }

    // ---- epilogue: normalize and scatter to (b, n, h*64+d) ----
    #pragma unroll
    for (int r = 0; r < 4; r++) {
        float inv = 1.f / l[r];
        int n = qt * 64 + ty * 4 + r;
        float* dst = g_x + ((size_t)(b * N_ + n)) * DIM_ + h * D_ + tx * 4;
        *(float4*)dst = make_float4(o[r][0] * inv, o[r][1] * inv,
                                    o[r][2] * inv, o[r][3] * inv);
    }
}

// ---------------------------------------------------------------------------
// Output projection: out[row][dout] = sum_c x[row][c] * W[dout][c] + bias[dout]
// Same 64x64 tile / 4x4 fragment scheme, K-tiles of 64 over DIM=768.
// ---------------------------------------------------------------------------
__global__ __launch_bounds__(256) void proj_kernel(
    const float* __restrict__ W, const float* __restrict__ bias,
    float* __restrict__ out)
{
    __shared__ float Xt[64][64];   // [k][row], swizzled
    __shared__ float Wt[64][64];   // [k][dout], swizzled

    int rt = blockIdx.x;   // 0..127 row tiles of 64
    int ct = blockIdx.y;   // 0..11  dout tiles of 64
    int tid = threadIdx.x;
    int tx = tid & 15, ty = tid >> 4;

    float acc[4][4];
    #pragma unroll
    for (int r = 0; r < 4; r++)
        #pragma unroll
        for (int c = 0; c < 4; c++) acc[r][c] = 0.f;

    int r  = tid >> 2;
    int c0 = (tid & 3) * 4;
    const float* xsrc = g_x + ((size_t)(rt * 64 + r)) * DIM_;
    const float* wsrc = W   + ((size_t)(ct * 64 + r)) * DIM_;

    for (int kt = 0; kt < DIM_ / 64; kt++) {
        __syncthreads();
        #pragma unroll
        for (int it = 0; it < 4; it++) {
            int d0 = c0 + it * 16;
            float4 xv = *(const float4*)(xsrc + kt * 64 + d0);
            float4 wv = *(const float4*)(wsrc + kt * 64 + d0);
            int pc = r ^ ((d0 & 12) << 1);
            float* dx = &Xt[d0][pc];
            dx[0] = xv.x; dx[64] = xv.y; dx[128] = xv.z; dx[192] = xv.w;
            float* dw = &Wt[d0][pc];
            dw[0] = wv.x; dw[64] = wv.y; dw[128] = wv.z; dw[192] = wv.w;
        }
        __syncthreads();

        #pragma unroll 16
        for (int d = 0; d < 64; d++) {
            int s = (d & 12) << 1;
            float4 a4 = *(const float4*)&Xt[d][(ty * 4) ^ s];
            float4 w4 = *(const float4*)&Wt[d][(tx * 4) ^ s];
            float aa[4] = {a4.x, a4.y, a4.z, a4.w};
            float wa[4] = {w4.x, w4.y, w4.z, w4.w};
            #pragma unroll
            for (int rr = 0; rr < 4; rr++)
                #pragma unroll
                for (int cc = 0; cc < 4; cc++) acc[rr][cc] += aa[rr] * wa[cc];
        }
    }

    float4 bv = *(const float4*)(bias + ct * 64 + tx * 4);
    #pragma unroll
    for (int rr = 0; rr < 4; rr++) {
        float* dst = out + ((size_t)(rt * 64 + ty * 4 + rr)) * DIM_ + ct * 64 + tx * 4;
        *(float4*)dst = make_float4(acc[rr][0] + bv.x, acc[rr][1] + bv.y,
                                    acc[rr][2] + bv.z, acc[rr][3] + bv.w);
    }
}

// ---------------------------------------------------------------------------
extern "C" void kernel_launch(void* const* d_in, const int* in_sizes, int n_in,
                              void* d_out, int out_size)
{
    const float* QKV  = (const float*)d_in[0];
    const float* qw   = (const float*)d_in[1];
    const float* qb   = (const float*)d_in[2];
    const float* kw   = (const float*)d_in[3];
    const float* kb   = (const float*)d_in[4];
    const float* W    = (const float*)d_in[5];
    const float* bias = (const float*)d_in[6];
    float* out = (float*)d_out;

    ln_kernel<<<(BH_ * N_) / 8, 256>>>(QKV, qw, qb, kw, kb);
    attn_kernel<<<dim3(N_ / 64, BH_), 256>>>(QKV);
    proj_kernel<<<dim3((B_ * N_) / 64, DIM_ / 64), 256>>>(W, bias, out);
}

// round 2
// speedup vs baseline: 1.0130x; 1.0130x over previous
#include <cuda_runtime.h>

#define B_   8
#define N_   1024
#define H_   12
#define D_   64
#define DIM_ 768
#define BH_  (B_*H_)

// Scratch (device globals: no allocation allowed in kernel_launch)
__device__ float g_q[(size_t)BH_ * N_ * D_];   // [b*H+h][n][d], pre-scaled by D^-0.5
__device__ float g_k[(size_t)BH_ * N_ * D_];   // [b*H+h][n][d]
__device__ float g_x[(size_t)B_ * N_ * DIM_];  // attention output, (b,n, h*64+d)

// ---- packed f32x2 helpers (SASS FFMA2 — ptxas never auto-generates) ----
typedef unsigned long long u64;

__device__ __forceinline__ u64 fma2(u64 a, u64 b, u64 c) {
    u64 d;
    asm("fma.rn.f32x2 %0, %1, %2, %3;" : "=l"(d) : "l"(a), "l"(b), "l"(c));
    return d;
}
__device__ __forceinline__ u64 mul2(u64 a, u64 b) {
    u64 d;
    asm("mul.rn.f32x2 %0, %1, %2;" : "=l"(d) : "l"(a), "l"(b));
    return d;
}
__device__ __forceinline__ u64 dup2(float x) {
    u64 r;
    unsigned u = __float_as_uint(x);
    asm("mov.b64 %0, {%1, %1};" : "=l"(r) : "r"(u));
    return r;
}
__device__ __forceinline__ float2 unpk2(u64 v) {
    float2 f;
    asm("mov.b64 {%0, %1}, %2;" : "=f"(f.x), "=f"(f.y) : "l"(v));
    return f;
}

// ---------------------------------------------------------------------------
// LayerNorm on q and k heads. One warp per (b,h,n): 64 elems -> 2 per lane.
// ---------------------------------------------------------------------------
__global__ __launch_bounds__(256) void ln_kernel(
    const float* __restrict__ QKV,
    const float* __restrict__ qw, const float* __restrict__ qb,
    const float* __restrict__ kw, const float* __restrict__ kb)
{
    int gw   = (blockIdx.x * blockDim.x + threadIdx.x) >> 5;
    int lane = threadIdx.x & 31;
    int n  = gw & (N_ - 1);
    int bh = gw >> 10;           // b*H + h
    int h  = bh % H_;
    int b  = bh / H_;

    const float* base = QKV + ((size_t)(b * N_ + n)) * (3 * DIM_) + h * D_;
    float q0 = base[lane],        q1 = base[lane + 32];
    float k0 = base[DIM_ + lane], k1 = base[DIM_ + lane + 32];

    float sq = q0 + q1, sk = k0 + k1;
    #pragma unroll
    for (int o = 16; o; o >>= 1) {
        sq += __shfl_xor_sync(0xffffffffu, sq, o);
        sk += __shfl_xor_sync(0xffffffffu, sk, o);
    }
    float muq = sq * (1.f / 64.f), muk = sk * (1.f / 64.f);
    float dq0 = q0 - muq, dq1 = q1 - muq;
    float dk0 = k0 - muk, dk1 = k1 - muk;
    float vq = dq0 * dq0 + dq1 * dq1;
    float vk = dk0 * dk0 + dk1 * dk1;
    #pragma unroll
    for (int o = 16; o; o >>= 1) {
        vq += __shfl_xor_sync(0xffffffffu, vq, o);
        vk += __shfl_xor_sync(0xffffffffu, vk, o);
    }
    float rq = rsqrtf(vq * (1.f / 64.f) + 1e-5f);
    float rk = rsqrtf(vk * (1.f / 64.f) + 1e-5f);
    const float scale = 0.125f;  // 64^-0.5 folded into q

    size_t ro = ((size_t)bh * N_ + n) * D_;
    g_q[ro + lane]      = (dq0 * rq * qw[lane]      + qb[lane])      * scale;
    g_q[ro + lane + 32] = (dq1 * rq * qw[lane + 32] + qb[lane + 32]) * scale;
    g_k[ro + lane]      =  dk0 * rk * kw[lane]      + kb[lane];
    g_k[ro + lane + 32] =  dk1 * rk * kw[lane + 32] + kb[lane + 32];
}

// ---------------------------------------------------------------------------
// Flash attention, BM=BN=64, 256 threads, 4x4 register fragments,
// inner products on the packed f32x2 pipe (2 MACs/lane/issue).
// ---------------------------------------------------------------------------
__global__ __launch_bounds__(256) void attn_kernel(const float* __restrict__ QKV)
{
    __shared__ float Qt [64][64];  // [d][qrow], swizzled
    __shared__ float KPt[64][64];  // phase 1: Kt [d][krow]; phase 2: Pt [j][i]
    __shared__ float Vs [64][64];  // [krow][d], natural

    int qt = blockIdx.x;           // 0..15 query tile
    int bh = blockIdx.y;           // 0..95
    int b = bh / H_, h = bh % H_;
    int tid = threadIdx.x;
    int tx = tid & 15, ty = tid >> 4;

    // ---- load Q tile (transposed + swizzled) ----
    {
        int r  = tid >> 2;             // tile row 0..63
        int c0 = (tid & 3) * 4;        // head-dim base
        const float* src = g_q + ((size_t)bh * N_ + qt * 64 + r) * D_;
        #pragma unroll
        for (int it = 0; it < 4; it++) {
            int d0 = c0 + it * 16;
            float4 v = *(const float4*)(src + d0);
            float* dst = &Qt[d0][r ^ ((d0 & 12) << 1)];
            dst[0] = v.x; dst[64] = v.y; dst[128] = v.z; dst[192] = v.w;
        }
    }

    float m[4], l[4];
    u64 o2[4][2];                  // packed output accumulators (4 rows x 2 col-pairs)
    #pragma unroll
    for (int r = 0; r < 4; r++) {
        m[r] = -1e30f; l[r] = 0.f;
        o2[r][0] = 0ull; o2[r][1] = 0ull;
    }

    const float* vbase = QKV + (size_t)b * N_ * (3 * DIM_) + 2 * DIM_ + h * D_;

    for (int kt = 0; kt < N_ / 64; kt++) {
        __syncthreads();  // prior iteration fully consumed KPt/Vs
        // ---- fill K tile (transposed+swizzled) and V tile (natural) ----
        {
            int r  = tid >> 2;
            int c0 = (tid & 3) * 4;
            const float* ksrc = g_k + ((size_t)bh * N_ + kt * 64 + r) * D_;
            const float* vsrc = vbase + (size_t)(kt * 64 + r) * (3 * DIM_);
            #pragma unroll
            for (int it = 0; it < 4; it++) {
                int d0 = c0 + it * 16;
                float4 kv = *(const float4*)(ksrc + d0);
                float* dst = &KPt[d0][r ^ ((d0 & 12) << 1)];
                dst[0] = kv.x; dst[64] = kv.y; dst[128] = kv.z; dst[192] = kv.w;
                *(float4*)&Vs[r][d0] = *(const float4*)(vsrc + d0);
            }
        }
        __syncthreads();

        // ---- S = Q * K^T on the f32x2 pipe ----
        u64 s2[4][2];
        #pragma unroll
        for (int r = 0; r < 4; r++) { s2[r][0] = 0ull; s2[r][1] = 0ull; }

        #pragma unroll 16
        for (int d = 0; d < 64; d++) {
            int s = (d & 12) << 1;
            float4    q4 = *(const float4*)   &Qt [d][(ty * 4) ^ s];
            ulonglong2 k2 = *(const ulonglong2*)&KPt[d][(tx * 4) ^ s];
            float qa[4] = {q4.x, q4.y, q4.z, q4.w};
            #pragma unroll
            for (int r = 0; r < 4; r++) {
                u64 qd = dup2(qa[r]);
                s2[r][0] = fma2(qd, k2.x, s2[r][0]);
                s2[r][1] = fma2(qd, k2.y, s2[r][1]);
            }
        }

        // unpack S for softmax
        float sf[4][4];
        #pragma unroll
        for (int r = 0; r < 4; r++) {
            float2 a = unpk2(s2[r][0]), bb = unpk2(s2[r][1]);
            sf[r][0] = a.x; sf[r][1] = a.y; sf[r][2] = bb.x; sf[r][3] = bb.y;
        }

        // ---- online softmax update ----
        #pragma unroll
        for (int r = 0; r < 4; r++) {
            float mt = fmaxf(fmaxf(sf[r][0], sf[r][1]), fmaxf(sf[r][2], sf[r][3]));
            #pragma unroll
            for (int off = 8; off; off >>= 1)
                mt = fmaxf(mt, __shfl_xor_sync(0xffffffffu, mt, off));
            float mn = fmaxf(m[r], mt);
            float al = __expf(m[r] - mn);
            m[r] = mn;

            float rs = 0.f;
            #pragma unroll
            for (int c = 0; c < 4; c++) {
                sf[r][c] = __expf(sf[r][c] - mn);
                rs += sf[r][c];
            }
            #pragma unroll
            for (int off = 8; off; off >>= 1)
                rs += __shfl_xor_sync(0xffffffffu, rs, off);
            l[r] = l[r] * al + rs;

            u64 ad = dup2(al);
            o2[r][0] = mul2(o2[r][0], ad);
            o2[r][1] = mul2(o2[r][1], ad);
        }

        __syncthreads();  // everyone done reading Kt before Pt overwrites it
        // ---- store P transposed [j][i], swizzled by j ----
        #pragma unroll
        for (int c = 0; c < 4; c++) {
            int j = tx * 4 + c;
            int s = (j & 12) << 1;
            *(float4*)&KPt[j][(ty * 4) ^ s] =
                make_float4(sf[0][c], sf[1][c], sf[2][c], sf[3][c]);
        }
        __syncthreads();

        // ---- O += P * V on the f32x2 pipe ----
        #pragma unroll 16
        for (int j = 0; j < 64; j++) {
            int s = (j & 12) << 1;
            float4    p4 = *(const float4*)   &KPt[j][(ty * 4) ^ s];
            ulonglong2 v2 = *(const ulonglong2*)&Vs[j][tx * 4];
            float pa[4] = {p4.x, p4.y, p4.z, p4.w};
            #pragma unroll
            for (int r = 0; r < 4; r++) {
                u64 pd = dup2(pa[r]);
                o2[r][0] = fma2(pd, v2.x, o2[r][0]);
                o2[r][1] = fma2(pd, v2.y, o2[r][1]);
            }
        }
    }

    // ---- epilogue: normalize and scatter to (b, n, h*64+d) ----
    #pragma unroll
    for (int r = 0; r < 4; r++) {
        float inv = 1.f / l[r];
        float2 a = unpk2(o2[r][0]), bb = unpk2(o2[r][1]);
        int n = qt * 64 + ty * 4 + r;
        float* dst = g_x + ((size_t)(b * N_ + n)) * DIM_ + h * D_ + tx * 4;
        *(float4*)dst = make_float4(a.x * inv, a.y * inv, bb.x * inv, bb.y * inv);
    }
}

// ---------------------------------------------------------------------------
// Output projection: out[row][dout] = sum_c x[row][c] * W[dout][c] + bias[dout]
// Same 64x64 tile / 4x4 fragment scheme, inner product on f32x2 pipe.
// ---------------------------------------------------------------------------
__global__ __launch_bounds__(256) void proj_kernel(
    const float* __restrict__ W, const float* __restrict__ bias,
    float* __restrict__ out)
{
    __shared__ float Xt[64][64];   // [k][row], swizzled
    __shared__ float Wt[64][64];   // [k][dout], swizzled

    int rt = blockIdx.x;   // 0..127 row tiles of 64
    int ct = blockIdx.y;   // 0..11  dout tiles of 64
    int tid = threadIdx.x;
    int tx = tid & 15, ty = tid >> 4;

    u64 acc2[4][2];
    #pragma unroll
    for (int r = 0; r < 4; r++) { acc2[r][0] = 0ull; acc2[r][1] = 0ull; }

    int r  = tid >> 2;
    int c0 = (tid & 3) * 4;
    const float* xsrc = g_x + ((size_t)(rt * 64 + r)) * DIM_;
    const float* wsrc = W   + ((size_t)(ct * 64 + r)) * DIM_;

    for (int kt = 0; kt < DIM_ / 64; kt++) {
        __syncthreads();
        #pragma unroll
        for (int it = 0; it < 4; it++) {
            int d0 = c0 + it * 16;
            float4 xv = *(const float4*)(xsrc + kt * 64 + d0);
            float4 wv = *(const float4*)(wsrc + kt * 64 + d0);
            int pc = r ^ ((d0 & 12) << 1);
            float* dx = &Xt[d0][pc];
            dx[0] = xv.x; dx[64] = xv.y; dx[128] = xv.z; dx[192] = xv.w;
            float* dw = &Wt[d0][pc];
            dw[0] = wv.x; dw[64] = wv.y; dw[128] = wv.z; dw[192] = wv.w;
        }
        __syncthreads();

        #pragma unroll 16
        for (int d = 0; d < 64; d++) {
            int s = (d & 12) << 1;
            float4    a4 = *(const float4*)   &Xt[d][(ty * 4) ^ s];
            ulonglong2 w2 = *(const ulonglong2*)&Wt[d][(tx * 4) ^ s];
            float aa[4] = {a4.x, a4.y, a4.z, a4.w};
            #pragma unroll
            for (int rr = 0; rr < 4; rr++) {
                u64 ad = dup2(aa[rr]);
                acc2[rr][0] = fma2(ad, w2.x, acc2[rr][0]);
                acc2[rr][1] = fma2(ad, w2.y, acc2[rr][1]);
            }
        }
    }

    float4 bv = *(const float4*)(bias + ct * 64 + tx * 4);
    #pragma unroll
    for (int rr = 0; rr < 4; rr++) {
        float2 a = unpk2(acc2[rr][0]), bb = unpk2(acc2[rr][1]);
        float* dst = out + ((size_t)(rt * 64 + ty * 4 + rr)) * DIM_ + ct * 64 + tx * 4;
        *(float4*)dst = make_float4(a.x + bv.x, a.y + bv.y,
                                    bb.x + bv.z, bb.y + bv.w);
    }
}

// ---------------------------------------------------------------------------
extern "C" void kernel_launch(void* const* d_in, const int* in_sizes, int n_in,
                              void* d_out, int out_size)
{
    const float* QKV  = (const float*)d_in[0];
    const float* qw   = (const float*)d_in[1];
    const float* qb   = (const float*)d_in[2];
    const float* kw   = (const float*)d_in[3];
    const float* kb   = (const float*)d_in[4];
    const float* W    = (const float*)d_in[5];
    const float* bias = (const float*)d_in[6];
    float* out = (float*)d_out;

    ln_kernel<<<(BH_ * N_) / 8, 256>>>(QKV, qw, qb, kw, kb);
    attn_kernel<<<dim3(N_ / 64, BH_), 256>>>(QKV);
    proj_kernel<<<dim3((B_ * N_) / 64, DIM_ / 64), 256>>>(W, bias, out);
}

// round 4
// speedup vs baseline: 2.3387x; 2.3087x over previous
#include <cuda_runtime.h>
#include <cuda_bf16.h>
#include <cstdint>

#define B_   8
#define N_   1024
#define H_   12
#define D_   64
#define DIM_ 768
#define BH_  (B_*H_)

// ---- split-bf16 scratch (device globals; no allocation in kernel_launch) ----
// layout: [bh][n][64] as 32 uint32 (bf16x2) per row
__device__ uint32_t g_q_hi[(size_t)BH_*N_*32], g_q_lo[(size_t)BH_*N_*32];
__device__ uint32_t g_k_hi[(size_t)BH_*N_*32], g_k_lo[(size_t)BH_*N_*32];
__device__ uint32_t g_v_hi[(size_t)BH_*N_*32], g_v_lo[(size_t)BH_*N_*32];
// attention output x: [b][n][768] as 384 uint32 per row
__device__ uint32_t g_x_hi[(size_t)B_*N_*384], g_x_lo[(size_t)B_*N_*384];

// ---------------------------------------------------------------------------
// helpers
// ---------------------------------------------------------------------------
__device__ __forceinline__ uint32_t smem_u32(const void* p) {
    uint32_t a;
    asm("{ .reg .u64 t; cvta.to.shared.u64 t, %1; cvt.u32.u64 %0, t; }" : "=r"(a) : "l"(p));
    return a;
}

// pack (x0,x1) to bf16x2 hi + residual bf16x2 lo
__device__ __forceinline__ void split2(float x0, float x1, uint32_t& hi, uint32_t& lo) {
    __nv_bfloat162 h = __floats2bfloat162_rn(x0, x1);
    float r0 = x0 - __bfloat162float(__low2bfloat16(h));
    float r1 = x1 - __bfloat162float(__high2bfloat16(h));
    __nv_bfloat162 l = __floats2bfloat162_rn(r0, r1);
    hi = *reinterpret_cast<uint32_t*>(&h);
    lo = *reinterpret_cast<uint32_t*>(&l);
}

// fast exp on FFMA/ALU pipes (no MUFU): exp(x) = 2^(x*log2e), x <= 0
__device__ __forceinline__ float expf_fast(float x) {
    float t = fmaxf(x * 1.4426950408889634f, -126.0f);
    float n = floorf(t);
    float f = t - n;
    float p =            1.8775767e-3f;
    p = fmaf(p, f, 8.9893397e-3f);
    p = fmaf(p, f, 5.5826318e-2f);
    p = fmaf(p, f, 2.4015361e-1f);
    p = fmaf(p, f, 6.9315308e-1f);
    p = fmaf(p, f, 9.9999994e-1f);
    return __int_as_float(__float_as_int(p) + (((int)n) << 23));
}

__device__ __forceinline__ void ldsm4(uint32_t* r, uint32_t addr) {
    asm volatile("ldmatrix.sync.aligned.m8n8.x4.shared.b16 {%0,%1,%2,%3}, [%4];"
        : "=r"(r[0]), "=r"(r[1]), "=r"(r[2]), "=r"(r[3]) : "r"(addr));
}
__device__ __forceinline__ void ldsm4t(uint32_t* r, uint32_t addr) {
    asm volatile("ldmatrix.sync.aligned.m8n8.x4.trans.shared.b16 {%0,%1,%2,%3}, [%4];"
        : "=r"(r[0]), "=r"(r[1]), "=r"(r[2]), "=r"(r[3]) : "r"(addr));
}
// D(16x8 f32) += A(16x16 bf16) * B(16x8 bf16)
__device__ __forceinline__ void mma_bf16(float* d, const uint32_t* a, uint32_t b0, uint32_t b1) {
    asm volatile(
        "mma.sync.aligned.m16n8k16.row.col.f32.bf16.bf16.f32 "
        "{%0,%1,%2,%3}, {%4,%5,%6,%7}, {%8,%9}, {%0,%1,%2,%3};"
        : "+f"(d[0]), "+f"(d[1]), "+f"(d[2]), "+f"(d[3])
        : "r"(a[0]), "r"(a[1]), "r"(a[2]), "r"(a[3]), "r"(b0), "r"(b1));
}

// ---------------------------------------------------------------------------
// LayerNorm(q,k) + bf16 hi/lo split of q,k,v. One warp per (b,h,n).
// Each lane owns the adjacent pair d = 2*lane, 2*lane+1.
// ---------------------------------------------------------------------------
__global__ __launch_bounds__(256) void ln_split_kernel(
    const float* __restrict__ QKV,
    const float* __restrict__ qw, const float* __restrict__ qb,
    const float* __restrict__ kw, const float* __restrict__ kb)
{
    int gw   = (blockIdx.x * blockDim.x + threadIdx.x) >> 5;
    int lane = threadIdx.x & 31;
    int n  = gw & (N_ - 1);
    int bh = gw >> 10;
    int h  = bh % H_;
    int b  = bh / H_;

    const float* base = QKV + ((size_t)(b * N_ + n)) * (3 * DIM_) + h * D_;
    float2 q = *(const float2*)(base + 2 * lane);
    float2 k = *(const float2*)(base + DIM_ + 2 * lane);
    float2 v = *(const float2*)(base + 2 * DIM_ + 2 * lane);

    float sq = q.x + q.y, sk = k.x + k.y;
    #pragma unroll
    for (int o = 16; o; o >>= 1) {
        sq += __shfl_xor_sync(0xffffffffu, sq, o);
        sk += __shfl_xor_sync(0xffffffffu, sk, o);
    }
    float muq = sq * (1.f / 64.f), muk = sk * (1.f / 64.f);
    float dq0 = q.x - muq, dq1 = q.y - muq;
    float dk0 = k.x - muk, dk1 = k.y - muk;
    float vq = dq0 * dq0 + dq1 * dq1;
    float vk = dk0 * dk0 + dk1 * dk1;
    #pragma unroll
    for (int o = 16; o; o >>= 1) {
        vq += __shfl_xor_sync(0xffffffffu, vq, o);
        vk += __shfl_xor_sync(0xffffffffu, vk, o);
    }
    float rq = rsqrtf(vq * (1.f / 64.f) + 1e-5f);
    float rk = rsqrtf(vk * (1.f / 64.f) + 1e-5f);
    const float scale = 0.125f;   // 64^-0.5 folded into q

    float q0 = (dq0 * rq * qw[2*lane]   + qb[2*lane])   * scale;
    float q1 = (dq1 * rq * qw[2*lane+1] + qb[2*lane+1]) * scale;
    float k0 =  dk0 * rk * kw[2*lane]   + kb[2*lane];
    float k1 =  dk1 * rk * kw[2*lane+1] + kb[2*lane+1];

    uint32_t hq, lq, hk, lk, hv, lv;
    split2(q0, q1, hq, lq);
    split2(k0, k1, hk, lk);
    split2(v.x, v.y, hv, lv);

    size_t ro = ((size_t)bh * N_ + n) * 32 + lane;
    g_q_hi[ro] = hq; g_q_lo[ro] = lq;
    g_k_hi[ro] = hk; g_k_lo[ro] = lk;
    g_v_hi[ro] = hv; g_v_lo[ro] = lv;
}

// ---------------------------------------------------------------------------
// Flash attention on mma.sync bf16 (split-3). CTA: 128 threads = 4 warps,
// each warp owns 16 query rows x all 64 keys. BM=BN=64.
// Smem tiles: 64 rows x 64 bf16, rows padded to 144B (conflict-free).
// ---------------------------------------------------------------------------
#define PITCH 144
#define T_SZ  (64 * PITCH)       // 9216 bytes per tile
#define OFF_QH 0
#define OFF_QL (1 * T_SZ)
#define OFF_KH (2 * T_SZ)        // shared K -> later P
#define OFF_KL (3 * T_SZ)
#define OFF_VH (4 * T_SZ)
#define OFF_VL (5 * T_SZ)
#define ATTN_SMEM (6 * T_SZ)

__global__ __launch_bounds__(128, 3) void attn_tc_kernel()
{
    extern __shared__ char sm[];
    uint32_t sb = smem_u32(sm);
    int tid = threadIdx.x, w = tid >> 5, lane = tid & 31;
    int qt = blockIdx.x, bh = blockIdx.y;
    int b = bh / H_, h = bh % H_;
    int i8 = lane & 7, sel = lane >> 3;
    int g = lane >> 2, t = lane & 3;

    // ldmatrix lane-address components
    int arow = ((sel & 1) << 3) + i8;   // A (row-major m16k16): + m0; col half:
    int acol = (sel >> 1) << 3;         //   + k0
    int brow = ((sel >> 1) << 3) + i8;  // B non-trans ([n][k] rows): + n0
    int bcol = (sel & 1) << 3;          //   + k0
    int vrow = ((sel & 1) << 3) + i8;   // B trans (V rows j): + j0
    int vcol = (sel >> 1) << 3;         //   + d0

    // ---- fill Q tiles ----
    for (int idx = tid; idx < 512; idx += 128) {
        int r = idx >> 3, c4 = idx & 7;
        size_t gi = ((size_t)bh * N_ + qt * 64 + r) * 8 + c4;
        *(uint4*)(sm + OFF_QH + r * PITCH + c4 * 16) = ((const uint4*)g_q_hi)[gi];
        *(uint4*)(sm + OFF_QL + r * PITCH + c4 * 16) = ((const uint4*)g_q_lo)[gi];
    }
    __syncthreads();

    // ---- preload Q fragments (constant across kt) ----
    uint32_t qh[4][4], ql[4][4];
    #pragma unroll
    for (int kc = 0; kc < 4; kc++) {
        uint32_t ad = sb + OFF_QH + (16 * w + arow) * PITCH + (16 * kc + acol) * 2;
        ldsm4(qh[kc], ad);
        ldsm4(ql[kc], ad + T_SZ);
    }

    float m0 = -1e30f, m1 = -1e30f, l0 = 0.f, l1 = 0.f;
    float o[8][4];
    #pragma unroll
    for (int s = 0; s < 8; s++)
        #pragma unroll
        for (int c = 0; c < 4; c++) o[s][c] = 0.f;

    for (int kt = 0; kt < N_ / 64; kt++) {
        __syncthreads();   // prev iter fully consumed V and P
        // ---- fill K (into KP) and V tiles ----
        for (int idx = tid; idx < 512; idx += 128) {
            int r = idx >> 3, c4 = idx & 7;
            size_t gi = ((size_t)bh * N_ + kt * 64 + r) * 8 + c4;
            char* dst = sm + r * PITCH + c4 * 16;
            *(uint4*)(dst + OFF_KH) = ((const uint4*)g_k_hi)[gi];
            *(uint4*)(dst + OFF_KL) = ((const uint4*)g_k_lo)[gi];
            *(uint4*)(dst + OFF_VH) = ((const uint4*)g_v_hi)[gi];
            *(uint4*)(dst + OFF_VL) = ((const uint4*)g_v_lo)[gi];
        }
        __syncthreads();

        // ---- S = Q*K^T (split-3) ----
        float s[8][4];
        #pragma unroll
        for (int ss = 0; ss < 8; ss++)
            #pragma unroll
            for (int c = 0; c < 4; c++) s[ss][c] = 0.f;

        #pragma unroll
        for (int kc = 0; kc < 4; kc++) {
            #pragma unroll
            for (int nb = 0; nb < 4; nb++) {
                uint32_t kh4[4], kl4[4];
                uint32_t kd = sb + OFF_KH + (nb * 16 + brow) * PITCH + (16 * kc + bcol) * 2;
                ldsm4(kh4, kd);
                ldsm4(kl4, kd + T_SZ);
                mma_bf16(s[2*nb],   qh[kc], kh4[0], kh4[1]);
                mma_bf16(s[2*nb],   qh[kc], kl4[0], kl4[1]);
                mma_bf16(s[2*nb],   ql[kc], kh4[0], kh4[1]);
                mma_bf16(s[2*nb+1], qh[kc], kh4[2], kh4[3]);
                mma_bf16(s[2*nb+1], qh[kc], kl4[2], kl4[3]);
                mma_bf16(s[2*nb+1], ql[kc], kh4[2], kh4[3]);
            }
        }

        // ---- online softmax (rows g and g+8 of this warp's 16) ----
        float mt0 = -1e30f, mt1 = -1e30f;
        #pragma unroll
        for (int ss = 0; ss < 8; ss++) {
            mt0 = fmaxf(mt0, fmaxf(s[ss][0], s[ss][1]));
            mt1 = fmaxf(mt1, fmaxf(s[ss][2], s[ss][3]));
        }
        mt0 = fmaxf(mt0, __shfl_xor_sync(0xffffffffu, mt0, 1));
        mt0 = fmaxf(mt0, __shfl_xor_sync(0xffffffffu, mt0, 2));
        mt1 = fmaxf(mt1, __shfl_xor_sync(0xffffffffu, mt1, 1));
        mt1 = fmaxf(mt1, __shfl_xor_sync(0xffffffffu, mt1, 2));
        float mn0 = fmaxf(m0, mt0), mn1 = fmaxf(m1, mt1);
        float a0 = expf_fast(m0 - mn0), a1 = expf_fast(m1 - mn1);
        m0 = mn0; m1 = mn1;

        float r0 = 0.f, r1 = 0.f;
        #pragma unroll
        for (int ss = 0; ss < 8; ss++) {
            s[ss][0] = expf_fast(s[ss][0] - mn0);
            s[ss][1] = expf_fast(s[ss][1] - mn0);
            s[ss][2] = expf_fast(s[ss][2] - mn1);
            s[ss][3] = expf_fast(s[ss][3] - mn1);
            r0 += s[ss][0] + s[ss][1];
            r1 += s[ss][2] + s[ss][3];
        }
        r0 += __shfl_xor_sync(0xffffffffu, r0, 1);
        r0 += __shfl_xor_sync(0xffffffffu, r0, 2);
        r1 += __shfl_xor_sync(0xffffffffu, r1, 1);
        r1 += __shfl_xor_sync(0xffffffffu, r1, 2);
        l0 = l0 * a0 + r0;
        l1 = l1 * a1 + r1;
        #pragma unroll
        for (int ss = 0; ss < 8; ss++) {
            o[ss][0] *= a0; o[ss][1] *= a0;
            o[ss][2] *= a1; o[ss][3] *= a1;
        }

        __syncthreads();   // all warps done reading K before P overwrites it
        // ---- store P (split) into KP buffer; warp-private rows ----
        {
            char* p0 = sm + (16 * w + g) * PITCH + t * 4;
            char* p1 = p0 + 8 * PITCH;
            #pragma unroll
            for (int ss = 0; ss < 8; ss++) {
                uint32_t hi, lo;
                split2(s[ss][0], s[ss][1], hi, lo);
                *(uint32_t*)(p0 + OFF_KH + ss * 16) = hi;
                *(uint32_t*)(p0 + OFF_KL + ss * 16) = lo;
                split2(s[ss][2], s[ss][3], hi, lo);
                *(uint32_t*)(p1 + OFF_KH + ss * 16) = hi;
                *(uint32_t*)(p1 + OFF_KL + ss * 16) = lo;
            }
        }
        __syncwarp();

        // ---- O += P*V (split-3); V via ldmatrix.trans ----
        #pragma unroll
        for (int kc = 0; kc < 4; kc++) {
            uint32_t ph4[4], pl4[4];
            uint32_t pd = sb + OFF_KH + (16 * w + arow) * PITCH + (16 * kc + acol) * 2;
            ldsm4(ph4, pd);
            ldsm4(pl4, pd + T_SZ);
            #pragma unroll
            for (int nb = 0; nb < 4; nb++) {
                uint32_t vh4[4], vl4[4];
                uint32_t vd = sb + OFF_VH + (16 * kc + vrow) * PITCH + (nb * 16 + vcol) * 2;
                ldsm4t(vh4, vd);
                ldsm4t(vl4, vd + T_SZ);
                mma_bf16(o[2*nb],   ph4, vh4[0], vh4[1]);
                mma_bf16(o[2*nb],   ph4, vl4[0], vl4[1]);
                mma_bf16(o[2*nb],   pl4, vh4[0], vh4[1]);
                mma_bf16(o[2*nb+1], ph4, vh4[2], vh4[3]);
                mma_bf16(o[2*nb+1], ph4, vl4[2], vl4[3]);
                mma_bf16(o[2*nb+1], pl4, vh4[2], vh4[3]);
            }
        }
    }

    // ---- epilogue: x = O/l, split to bf16 hi/lo, store ----
    float inv0 = 1.f / l0, inv1 = 1.f / l1;
    int n0 = qt * 64 + 16 * w + g;
    size_t ro0 = ((size_t)(b * N_ + n0)) * 384 + h * 32 + t;
    size_t ro1 = ro0 + (size_t)8 * 384;
    #pragma unroll
    for (int ss = 0; ss < 8; ss++) {
        uint32_t hi, lo;
        split2(o[ss][0] * inv0, o[ss][1] * inv0, hi, lo);
        g_x_hi[ro0 + ss * 4] = hi;
        g_x_lo[ro0 + ss * 4] = lo;
        split2(o[ss][2] * inv1, o[ss][3] * inv1, hi, lo);
        g_x_hi[ro1 + ss * 4] = hi;
        g_x_lo[ro1 + ss * 4] = lo;
    }
}

// ---------------------------------------------------------------------------
// Projection on mma.sync bf16 (split-3): out = X * W^T + bias.
// CTA: 4 warps, tile 64m x 64n, K-loop 12 x 64.
// ---------------------------------------------------------------------------
#define POFF_XH 0
#define POFF_XL (1 * T_SZ)
#define POFF_WH (2 * T_SZ)
#define POFF_WL (3 * T_SZ)

__global__ __launch_bounds__(128) void proj_tc_kernel(
    const float* __restrict__ W, const float* __restrict__ bias,
    float* __restrict__ out)
{
    __shared__ alignas(16) char sm[4 * T_SZ];
    uint32_t sb = smem_u32(sm);
    int tid = threadIdx.x, w = tid >> 5, lane = tid & 31;
    int rt = blockIdx.x, ct = blockIdx.y;
    int i8 = lane & 7, sel = lane >> 3;
    int g = lane >> 2, t = lane & 3;

    int arow = ((sel & 1) << 3) + i8;
    int acol = (sel >> 1) << 3;
    int brow = ((sel >> 1) << 3) + i8;
    int bcol = (sel & 1) << 3;

    float acc[8][4];
    #pragma unroll
    for (int s = 0; s < 8; s++)
        #pragma unroll
        for (int c = 0; c < 4; c++) acc[s][c] = 0.f;

    for (int kc = 0; kc < 12; kc++) {
        __syncthreads();
        // X tiles: direct uint4 copies of pre-split bf16
        for (int idx = tid; idx < 512; idx += 128) {
            int r = idx >> 3, c4 = idx & 7;
            size_t gi = ((size_t)(rt * 64 + r)) * 96 + kc * 8 + c4;
            char* dst = sm + r * PITCH + c4 * 16;
            *(uint4*)(dst + POFF_XH) = ((const uint4*)g_x_hi)[gi];
            *(uint4*)(dst + POFF_XL) = ((const uint4*)g_x_lo)[gi];
        }
        // W tiles: split fp32 -> bf16 hi/lo
        for (int idx = tid; idx < 2048; idx += 128) {
            int r = idx >> 5, p = idx & 31;
            float2 wv = *(const float2*)(W + (size_t)(ct * 64 + r) * DIM_ + kc * 64 + 2 * p);
            uint32_t hi, lo;
            split2(wv.x, wv.y, hi, lo);
            char* dst = sm + r * PITCH + p * 4;
            *(uint32_t*)(dst + POFF_WH) = hi;
            *(uint32_t*)(dst + POFF_WL) = lo;
        }
        __syncthreads();

        #pragma unroll
        for (int k2 = 0; k2 < 4; k2++) {
            uint32_t ah4[4], al4[4];
            uint32_t ad = sb + POFF_XH + (16 * w + arow) * PITCH + (16 * k2 + acol) * 2;
            ldsm4(ah4, ad);
            ldsm4(al4, ad + T_SZ);
            #pragma unroll
            for (int nb = 0; nb < 4; nb++) {
                uint32_t wh4[4], wl4[4];
                uint32_t wd = sb + POFF_WH + (nb * 16 + brow) * PITCH + (16 * k2 + bcol) * 2;
                ldsm4(wh4, wd);
                ldsm4(wl4, wd + T_SZ);
                mma_bf16(acc[2*nb],   ah4, wh4[0], wh4[1]);
                mma_bf16(acc[2*nb],   ah4, wl4[0], wl4[1]);
                mma_bf16(acc[2*nb],   al4, wh4[0], wh4[1]);
                mma_bf16(acc[2*nb+1], ah4, wh4[2], wh4[3]);
                mma_bf16(acc[2*nb+1], ah4, wl4[2], wl4[3]);
                mma_bf16(acc[2*nb+1], al4, wh4[2], wh4[3]);
            }
        }
    }

    // epilogue
    int row = rt * 64 + 16 * w + g;
    #pragma unroll
    for (int ss = 0; ss < 8; ss++) {
        int col = ct * 64 + 8 * ss + 2 * t;
        float2 bv = *(const float2*)(bias + col);
        *(float2*)(out + (size_t)row * DIM_ + col) =
            make_float2(acc[ss][0] + bv.x, acc[ss][1] + bv.y);
        *(float2*)(out + (size_t)(row + 8) * DIM_ + col) =
            make_float2(acc[ss][2] + bv.x, acc[ss][3] + bv.y);
    }
}

// ---------------------------------------------------------------------------
extern "C" void kernel_launch(void* const* d_in, const int* in_sizes, int n_in,
                              void* d_out, int out_size)
{
    const float* QKV  = (const float*)d_in[0];
    const float* qw   = (const float*)d_in[1];
    const float* qb   = (const float*)d_in[2];
    const float* kw   = (const float*)d_in[3];
    const float* kb   = (const float*)d_in[4];
    const float* W    = (const float*)d_in[5];
    const float* bias = (const float*)d_in[6];
    float* out = (float*)d_out;

    cudaFuncSetAttribute(attn_tc_kernel,
                         cudaFuncAttributeMaxDynamicSharedMemorySize, ATTN_SMEM);

    ln_split_kernel<<<(BH_ * N_) / 8, 256>>>(QKV, qw, qb, kw, kb);
    attn_tc_kernel<<<dim3(N_ / 64, BH_), 128, ATTN_SMEM>>>();
    proj_tc_kernel<<<dim3((B_ * N_) / 64, DIM_ / 64), 128>>>(W, bias, out);
}

// round 5
// speedup vs baseline: 2.8151x; 1.2037x over previous
#include <cuda_runtime.h>
#include <cuda_bf16.h>
#include <cstdint>

#define B_   8
#define N_   1024
#define H_   12
#define D_   64
#define DIM_ 768
#define BH_  (B_*H_)

// ---- split-bf16 scratch (device globals; no allocation in kernel_launch) ----
__device__ uint32_t g_q_hi[(size_t)BH_*N_*32], g_q_lo[(size_t)BH_*N_*32];
__device__ uint32_t g_k_hi[(size_t)BH_*N_*32], g_k_lo[(size_t)BH_*N_*32];
__device__ uint32_t g_v_hi[(size_t)BH_*N_*32], g_v_lo[(size_t)BH_*N_*32];
__device__ uint32_t g_x_hi[(size_t)B_*N_*384], g_x_lo[(size_t)B_*N_*384];
__device__ uint32_t g_w_hi[(size_t)DIM_*384],  g_w_lo[(size_t)DIM_*384];

// ---------------------------------------------------------------------------
// helpers
// ---------------------------------------------------------------------------
__device__ __forceinline__ uint32_t smem_u32(const void* p) {
    uint32_t a;
    asm("{ .reg .u64 t; cvta.to.shared.u64 t, %1; cvt.u32.u64 %0, t; }" : "=r"(a) : "l"(p));
    return a;
}
__device__ __forceinline__ void split2(float x0, float x1, uint32_t& hi, uint32_t& lo) {
    __nv_bfloat162 h = __floats2bfloat162_rn(x0, x1);
    float r0 = x0 - __bfloat162float(__low2bfloat16(h));
    float r1 = x1 - __bfloat162float(__high2bfloat16(h));
    __nv_bfloat162 l = __floats2bfloat162_rn(r0, r1);
    hi = *reinterpret_cast<uint32_t*>(&h);
    lo = *reinterpret_cast<uint32_t*>(&l);
}
// fast exp on FFMA/ALU pipes (no MUFU)
__device__ __forceinline__ float expf_fast(float x) {
    float t = fmaxf(x * 1.4426950408889634f, -126.0f);
    float n = floorf(t);
    float f = t - n;
    float p =            1.8775767e-3f;
    p = fmaf(p, f, 8.9893397e-3f);
    p = fmaf(p, f, 5.5826318e-2f);
    p = fmaf(p, f, 2.4015361e-1f);
    p = fmaf(p, f, 6.9315308e-1f);
    p = fmaf(p, f, 9.9999994e-1f);
    return __int_as_float(__float_as_int(p) + (((int)n) << 23));
}
__device__ __forceinline__ void ldsm4(uint32_t* r, uint32_t addr) {
    asm volatile("ldmatrix.sync.aligned.m8n8.x4.shared.b16 {%0,%1,%2,%3}, [%4];"
        : "=r"(r[0]), "=r"(r[1]), "=r"(r[2]), "=r"(r[3]) : "r"(addr));
}
__device__ __forceinline__ void ldsm4t(uint32_t* r, uint32_t addr) {
    asm volatile("ldmatrix.sync.aligned.m8n8.x4.trans.shared.b16 {%0,%1,%2,%3}, [%4];"
        : "=r"(r[0]), "=r"(r[1]), "=r"(r[2]), "=r"(r[3]) : "r"(addr));
}
__device__ __forceinline__ void mma_bf16(float* d, const uint32_t* a, uint32_t b0, uint32_t b1) {
    asm volatile(
        "mma.sync.aligned.m16n8k16.row.col.f32.bf16.bf16.f32 "
        "{%0,%1,%2,%3}, {%4,%5,%6,%7}, {%8,%9}, {%0,%1,%2,%3};"
        : "+f"(d[0]), "+f"(d[1]), "+f"(d[2]), "+f"(d[3])
        : "r"(a[0]), "r"(a[1]), "r"(a[2]), "r"(a[3]), "r"(b0), "r"(b1));
}
__device__ __forceinline__ void cpa16(uint32_t dst, const void* src) {
    asm volatile("cp.async.cg.shared.global [%0], [%1], 16;" :: "r"(dst), "l"(src) : "memory");
}
#define CP_COMMIT() asm volatile("cp.async.commit_group;" ::: "memory")
#define CP_WAIT1()  asm volatile("cp.async.wait_group 1;" ::: "memory")

// ---------------------------------------------------------------------------
// LayerNorm(q,k) + bf16 hi/lo split of q,k,v. One warp per (b,h,n).
// ---------------------------------------------------------------------------
__global__ __launch_bounds__(256) void ln_split_kernel(
    const float* __restrict__ QKV,
    const float* __restrict__ qw, const float* __restrict__ qb,
    const float* __restrict__ kw, const float* __restrict__ kb)
{
    int gw   = (blockIdx.x * blockDim.x + threadIdx.x) >> 5;
    int lane = threadIdx.x & 31;
    int n  = gw & (N_ - 1);
    int bh = gw >> 10;
    int h  = bh % H_;
    int b  = bh / H_;

    const float* base = QKV + ((size_t)(b * N_ + n)) * (3 * DIM_) + h * D_;
    float2 q = *(const float2*)(base + 2 * lane);
    float2 k = *(const float2*)(base + DIM_ + 2 * lane);
    float2 v = *(const float2*)(base + 2 * DIM_ + 2 * lane);

    float sq = q.x + q.y, sk = k.x + k.y;
    #pragma unroll
    for (int o = 16; o; o >>= 1) {
        sq += __shfl_xor_sync(0xffffffffu, sq, o);
        sk += __shfl_xor_sync(0xffffffffu, sk, o);
    }
    float muq = sq * (1.f / 64.f), muk = sk * (1.f / 64.f);
    float dq0 = q.x - muq, dq1 = q.y - muq;
    float dk0 = k.x - muk, dk1 = k.y - muk;
    float vq = dq0 * dq0 + dq1 * dq1;
    float vk = dk0 * dk0 + dk1 * dk1;
    #pragma unroll
    for (int o = 16; o; o >>= 1) {
        vq += __shfl_xor_sync(0xffffffffu, vq, o);
        vk += __shfl_xor_sync(0xffffffffu, vk, o);
    }
    float rq = rsqrtf(vq * (1.f / 64.f) + 1e-5f);
    float rk = rsqrtf(vk * (1.f / 64.f) + 1e-5f);
    const float scale = 0.125f;

    float q0 = (dq0 * rq * qw[2*lane]   + qb[2*lane])   * scale;
    float q1 = (dq1 * rq * qw[2*lane+1] + qb[2*lane+1]) * scale;
    float k0 =  dk0 * rk * kw[2*lane]   + kb[2*lane];
    float k1 =  dk1 * rk * kw[2*lane+1] + kb[2*lane+1];

    uint32_t hq, lq, hk, lk, hv, lv;
    split2(q0, q1, hq, lq);
    split2(k0, k1, hk, lk);
    split2(v.x, v.y, hv, lv);

    size_t ro = ((size_t)bh * N_ + n) * 32 + lane;
    g_q_hi[ro] = hq; g_q_lo[ro] = lq;
    g_k_hi[ro] = hk; g_k_lo[ro] = lk;
    g_v_hi[ro] = hv; g_v_lo[ro] = lv;
}

// ---------------------------------------------------------------------------
// Pre-split projection weights to bf16 hi/lo (once; removes 128x redundancy)
// ---------------------------------------------------------------------------
__global__ __launch_bounds__(256) void w_split_kernel(const float* __restrict__ W)
{
    int i = blockIdx.x * 256 + threadIdx.x;   // pair index, 294912 total
    float2 w = *(const float2*)(W + 2 * i);
    uint32_t hi, lo;
    split2(w.x, w.y, hi, lo);
    g_w_hi[i] = hi; g_w_lo[i] = lo;
}

// ---------------------------------------------------------------------------
// Flash attention v2: mma.sync bf16 split-3, P kept in registers,
// 2-stage cp.async pipeline for K/V tiles. 128 threads, BM=BN=64.
// ---------------------------------------------------------------------------
#define PITCH  144
#define T_SZ   (64 * PITCH)      // 9216
#define STG_SZ (4 * T_SZ)        // KH,KL,VH,VL per stage = 36864
#define ATTN_SMEM (2 * STG_SZ)   // 73728; Q overlays stage 1 during prologue
#define OKH 0
#define OKL (1 * T_SZ)
#define OVH (2 * T_SZ)
#define OVL (3 * T_SZ)

__global__ __launch_bounds__(128, 3) void attn_tc_kernel()
{
    extern __shared__ char sm[];
    uint32_t sb = smem_u32(sm);
    int tid = threadIdx.x, w = tid >> 5, lane = tid & 31;
    int qt = blockIdx.x, bh = blockIdx.y;
    int b = bh / H_, h = bh % H_;
    int i8 = lane & 7, sel = lane >> 3;
    int g = lane >> 2, t = lane & 3;

    int arow = ((sel & 1) << 3) + i8;   // A frag rows
    int acol = (sel >> 1) << 3;
    int brow = ((sel >> 1) << 3) + i8;  // B frag (K rows)
    int bcol = (sel & 1) << 3;
    int vrow = ((sel & 1) << 3) + i8;   // B trans (V rows)
    int vcol = (sel >> 1) << 3;

    int fr  = tid >> 3;                 // fill row base (row = fr + 16*i)
    int fc  = tid & 7;                  // fill col (uint4 within row)
    size_t grow = (size_t)bh * N_;

    // ---- prologue: async-fill K/V stage 0, regular-fill Q into stage-1 area ----
    #pragma unroll
    for (int i = 0; i < 4; i++) {
        int r = fr + 16 * i;
        size_t gi = (grow + 0 * 64 + r) * 8 + fc;
        uint32_t d = sb + r * PITCH + fc * 16;
        cpa16(d + OKH, (const char*)g_k_hi + gi * 16);
        cpa16(d + OKL, (const char*)g_k_lo + gi * 16);
        cpa16(d + OVH, (const char*)g_v_hi + gi * 16);
        cpa16(d + OVL, (const char*)g_v_lo + gi * 16);
    }
    CP_COMMIT();
    #pragma unroll
    for (int i = 0; i < 4; i++) {
        int r = fr + 16 * i;
        size_t gi = (grow + qt * 64 + r) * 8 + fc;
        char* d = sm + STG_SZ + r * PITCH + fc * 16;
        *(uint4*)(d)        = ((const uint4*)g_q_hi)[gi];
        *(uint4*)(d + T_SZ) = ((const uint4*)g_q_lo)[gi];
    }
    __syncthreads();

    // ---- preload Q fragments (then stage-1 area is free for the pipeline) ----
    uint32_t qh[4][4], ql[4][4];
    #pragma unroll
    for (int kc = 0; kc < 4; kc++) {
        uint32_t ad = sb + STG_SZ + (16 * w + arow) * PITCH + (16 * kc + acol) * 2;
        ldsm4(qh[kc], ad);
        ldsm4(ql[kc], ad + T_SZ);
    }
    __syncthreads();   // Q frag loads done before stage-1 refill

    float m0 = -1e30f, m1 = -1e30f, l0 = 0.f, l1 = 0.f;
    float o[8][4];
    #pragma unroll
    for (int s = 0; s < 8; s++)
        #pragma unroll
        for (int c = 0; c < 4; c++) o[s][c] = 0.f;

    for (int kt = 0; kt < N_ / 64; kt++) {
        uint32_t cb = sb + (uint32_t)(kt & 1) * STG_SZ;   // current buffer

        // ---- async-prefetch next K/V tile into the other buffer ----
        if (kt + 1 < N_ / 64) {
            uint32_t nb_ = sb + (uint32_t)((kt + 1) & 1) * STG_SZ;
            #pragma unroll
            for (int i = 0; i < 4; i++) {
                int r = fr + 16 * i;
                size_t gi = (grow + (kt + 1) * 64 + r) * 8 + fc;
                uint32_t d = nb_ + r * PITCH + fc * 16;
                cpa16(d + OKH, (const char*)g_k_hi + gi * 16);
                cpa16(d + OKL, (const char*)g_k_lo + gi * 16);
                cpa16(d + OVH, (const char*)g_v_hi + gi * 16);
                cpa16(d + OVL, (const char*)g_v_lo + gi * 16);
            }
        }
        CP_COMMIT();
        CP_WAIT1();        // current stage complete (≤1 group in flight)
        __syncthreads();

        // ---- S = Q*K^T (split-3) ----
        float s[8][4];
        #pragma unroll
        for (int ss = 0; ss < 8; ss++)
            #pragma unroll
            for (int c = 0; c < 4; c++) s[ss][c] = 0.f;

        #pragma unroll
        for (int kc = 0; kc < 4; kc++) {
            #pragma unroll
            for (int nb = 0; nb < 4; nb++) {
                uint32_t kh4[4], kl4[4];
                uint32_t kd = cb + OKH + (nb * 16 + brow) * PITCH + (16 * kc + bcol) * 2;
                ldsm4(kh4, kd);
                ldsm4(kl4, kd + T_SZ);
                mma_bf16(s[2*nb],   qh[kc], kh4[0], kh4[1]);
                mma_bf16(s[2*nb],   qh[kc], kl4[0], kl4[1]);
                mma_bf16(s[2*nb],   ql[kc], kh4[0], kh4[1]);
                mma_bf16(s[2*nb+1], qh[kc], kh4[2], kh4[3]);
                mma_bf16(s[2*nb+1], qh[kc], kl4[2], kl4[3]);
                mma_bf16(s[2*nb+1], ql[kc], kh4[2], kh4[3]);
            }
        }

        // ---- online softmax ----
        float mt0 = -1e30f, mt1 = -1e30f;
        #pragma unroll
        for (int ss = 0; ss < 8; ss++) {
            mt0 = fmaxf(mt0, fmaxf(s[ss][0], s[ss][1]));
            mt1 = fmaxf(mt1, fmaxf(s[ss][2], s[ss][3]));
        }
        mt0 = fmaxf(mt0, __shfl_xor_sync(0xffffffffu, mt0, 1));
        mt0 = fmaxf(mt0, __shfl_xor_sync(0xffffffffu, mt0, 2));
        mt1 = fmaxf(mt1, __shfl_xor_sync(0xffffffffu, mt1, 1));
        mt1 = fmaxf(mt1, __shfl_xor_sync(0xffffffffu, mt1, 2));
        float mn0 = fmaxf(m0, mt0), mn1 = fmaxf(m1, mt1);
        float a0 = expf_fast(m0 - mn0), a1 = expf_fast(m1 - mn1);
        m0 = mn0; m1 = mn1;

        float r0 = 0.f, r1 = 0.f;
        #pragma unroll
        for (int ss = 0; ss < 8; ss++) {
            s[ss][0] = expf_fast(s[ss][0] - mn0);
            s[ss][1] = expf_fast(s[ss][1] - mn0);
            s[ss][2] = expf_fast(s[ss][2] - mn1);
            s[ss][3] = expf_fast(s[ss][3] - mn1);
            r0 += s[ss][0] + s[ss][1];
            r1 += s[ss][2] + s[ss][3];
        }
        r0 += __shfl_xor_sync(0xffffffffu, r0, 1);
        r0 += __shfl_xor_sync(0xffffffffu, r0, 2);
        r1 += __shfl_xor_sync(0xffffffffu, r1, 1);
        r1 += __shfl_xor_sync(0xffffffffu, r1, 2);
        l0 = l0 * a0 + r0;
        l1 = l1 * a1 + r1;
        #pragma unroll
        for (int ss = 0; ss < 8; ss++) {
            o[ss][0] *= a0; o[ss][1] *= a0;
            o[ss][2] *= a1; o[ss][3] *= a1;
        }

        // ---- O += P*V: P packed straight from S fragments (FA2 trick) ----
        #pragma unroll
        for (int kc = 0; kc < 4; kc++) {
            uint32_t ph[4], pl[4];
            split2(s[2*kc][0],   s[2*kc][1],   ph[0], pl[0]);
            split2(s[2*kc][2],   s[2*kc][3],   ph[1], pl[1]);
            split2(s[2*kc+1][0], s[2*kc+1][1], ph[2], pl[2]);
            split2(s[2*kc+1][2], s[2*kc+1][3], ph[3], pl[3]);
            #pragma unroll
            for (int nb = 0; nb < 4; nb++) {
                uint32_t vh4[4], vl4[4];
                uint32_t vd = cb + OVH + (16 * kc + vrow) * PITCH + (nb * 16 + vcol) * 2;
                ldsm4t(vh4, vd);
                ldsm4t(vl4, vd + T_SZ);
                mma_bf16(o[2*nb],   ph, vh4[0], vh4[1]);
                mma_bf16(o[2*nb],   ph, vl4[0], vl4[1]);
                mma_bf16(o[2*nb],   pl, vh4[0], vh4[1]);
                mma_bf16(o[2*nb+1], ph, vh4[2], vh4[3]);
                mma_bf16(o[2*nb+1], ph, vl4[2], vl4[3]);
                mma_bf16(o[2*nb+1], pl, vh4[2], vh4[3]);
            }
        }
        __syncthreads();   // buffer consumed before it is refilled at kt+2
    }

    // ---- epilogue: x = O/l, split to bf16 hi/lo ----
    float inv0 = 1.f / l0, inv1 = 1.f / l1;
    int n0 = qt * 64 + 16 * w + g;
    size_t ro0 = ((size_t)(b * N_ + n0)) * 384 + h * 32 + t;
    size_t ro1 = ro0 + (size_t)8 * 384;
    #pragma unroll
    for (int ss = 0; ss < 8; ss++) {
        uint32_t hi, lo;
        split2(o[ss][0] * inv0, o[ss][1] * inv0, hi, lo);
        g_x_hi[ro0 + ss * 4] = hi;
        g_x_lo[ro0 + ss * 4] = lo;
        split2(o[ss][2] * inv1, o[ss][3] * inv1, hi, lo);
        g_x_hi[ro1 + ss * 4] = hi;
        g_x_lo[ro1 + ss * 4] = lo;
    }
}

// ---------------------------------------------------------------------------
// Projection v2: pre-split X and W, 2-stage cp.async, split-3 mma.
// Tiles: XH,XL,WH,WL per stage. 64m x 64n, 12 K-iters.
// ---------------------------------------------------------------------------
#define OXH 0
#define OXL (1 * T_SZ)
#define OWH (2 * T_SZ)
#define OWL (3 * T_SZ)
#define PROJ_SMEM (2 * STG_SZ)

__global__ __launch_bounds__(128, 3) void proj_tc_kernel(
    const float* __restrict__ bias, float* __restrict__ out)
{
    extern __shared__ char sm[];
    uint32_t sb = smem_u32(sm);
    int tid = threadIdx.x, w = tid >> 5, lane = tid & 31;
    int rt = blockIdx.x, ct = blockIdx.y;
    int i8 = lane & 7, sel = lane >> 3;
    int g = lane >> 2, t = lane & 3;

    int arow = ((sel & 1) << 3) + i8;
    int acol = (sel >> 1) << 3;
    int brow = ((sel >> 1) << 3) + i8;
    int bcol = (sel & 1) << 3;

    int fr = tid >> 3, fc = tid & 7;

    auto fill = [&](int kc, uint32_t buf) {
        #pragma unroll
        for (int i = 0; i < 4; i++) {
            int r = fr + 16 * i;
            size_t xi = ((size_t)(rt * 64 + r)) * 96 + kc * 8 + fc;
            size_t wi = ((size_t)(ct * 64 + r)) * 96 + kc * 8 + fc;
            uint32_t d = buf + r * PITCH + fc * 16;
            cpa16(d + OXH, (const char*)g_x_hi + xi * 16);
            cpa16(d + OXL, (const char*)g_x_lo + xi * 16);
            cpa16(d + OWH, (const char*)g_w_hi + wi * 16);
            cpa16(d + OWL, (const char*)g_w_lo + wi * 16);
        }
    };

    float acc[8][4];
    #pragma unroll
    for (int s = 0; s < 8; s++)
        #pragma unroll
        for (int c = 0; c < 4; c++) acc[s][c] = 0.f;

    fill(0, sb);
    CP_COMMIT();

    for (int kc = 0; kc < 12; kc++) {
        uint32_t cb = sb + (uint32_t)(kc & 1) * STG_SZ;
        if (kc + 1 < 12) fill(kc + 1, sb + (uint32_t)((kc + 1) & 1) * STG_SZ);
        CP_COMMIT();
        CP_WAIT1();
        __syncthreads();

        #pragma unroll
        for (int k2 = 0; k2 < 4; k2++) {
            uint32_t ah4[4], al4[4];
            uint32_t ad = cb + OXH + (16 * w + arow) * PITCH + (16 * k2 + acol) * 2;
            ldsm4(ah4, ad);
            ldsm4(al4, ad + T_SZ);
            #pragma unroll
            for (int nb = 0; nb < 4; nb++) {
                uint32_t wh4[4], wl4[4];
                uint32_t wd = cb + OWH + (nb * 16 + brow) * PITCH + (16 * k2 + bcol) * 2;
                ldsm4(wh4, wd);
                ldsm4(wl4, wd + T_SZ);
                mma_bf16(acc[2*nb],   ah4, wh4[0], wh4[1]);
                mma_bf16(acc[2*nb],   ah4, wl4[0], wl4[1]);
                mma_bf16(acc[2*nb],   al4, wh4[0], wh4[1]);
                mma_bf16(acc[2*nb+1], ah4, wh4[2], wh4[3]);
                mma_bf16(acc[2*nb+1], ah4, wl4[2], wl4[3]);
                mma_bf16(acc[2*nb+1], al4, wh4[2], wh4[3]);
            }
        }
        __syncthreads();
    }

    int row = rt * 64 + 16 * w + g;
    #pragma unroll
    for (int ss = 0; ss < 8; ss++) {
        int col = ct * 64 + 8 * ss + 2 * t;
        float2 bv = *(const float2*)(bias + col);
        *(float2*)(out + (size_t)row * DIM_ + col) =
            make_float2(acc[ss][0] + bv.x, acc[ss][1] + bv.y);
        *(float2*)(out + (size_t)(row + 8) * DIM_ + col) =
            make_float2(acc[ss][2] + bv.x, acc[ss][3] + bv.y);
    }
}

// ---------------------------------------------------------------------------
extern "C" void kernel_launch(void* const* d_in, const int* in_sizes, int n_in,
                              void* d_out, int out_size)
{
    const float* QKV  = (const float*)d_in[0];
    const float* qw   = (const float*)d_in[1];
    const float* qb   = (const float*)d_in[2];
    const float* kw   = (const float*)d_in[3];
    const float* kb   = (const float*)d_in[4];
    const float* W    = (const float*)d_in[5];
    const float* bias = (const float*)d_in[6];
    float* out = (float*)d_out;

    cudaFuncSetAttribute(attn_tc_kernel,
                         cudaFuncAttributeMaxDynamicSharedMemorySize, ATTN_SMEM);
    cudaFuncSetAttribute(proj_tc_kernel,
                         cudaFuncAttributeMaxDynamicSharedMemorySize, PROJ_SMEM);

    ln_split_kernel<<<(BH_ * N_) / 8, 256>>>(QKV, qw, qb, kw, kb);
    w_split_kernel<<<(DIM_ * DIM_ / 2) / 256, 256>>>(W);
    attn_tc_kernel<<<dim3(N_ / 64, BH_), 128, ATTN_SMEM>>>();
    proj_tc_kernel<<<dim3((B_ * N_) / 64, DIM_ / 64), 128, PROJ_SMEM>>>(bias, out);
}